// round 12
// baseline (speedup 1.0000x reference)
#include <cuda_runtime.h>
#include <cuda_fp16.h>
#include <cstdint>

#define KDIM 1024
#define IDIM 64
#define ODIM 1024
#define THREADS 256
#define KC 32                   // k per chunk
#define NCHUNK (KDIM / KC)      // 32

// 64B-row tiles, SW64 XOR swizzle (conflict-free for ldmatrix phases)
#define SWZ64(o) ((uint32_t)(o) ^ ((((uint32_t)(o)) >> 3) & 0x30))
#define TILE_A 8192             // A fp16 tile: 128 x 32 fp16
#define TILE_B16 8192           // B fp16 tile: 128 x 32 fp16

#define OFF_A 0                      // 3 buffers: +0, +8192, +16384
#define OFF_B16 (3 * TILE_A)         // 24576: 2 buffers
#define SMEM_DYN (OFF_B16 + 2 * TILE_B16)   // 40960

// Pre-converted x: tile (i, ch) = 8 KB at ((i*32+ch)*8192); swizzled
// [b(128) x 32 fp16] rows of 64B.
__device__ unsigned char g_xh[64 * 32 * 8192];

static __device__ __forceinline__ uint32_t smem_u32(const void* p) {
    uint32_t a;
    asm("{ .reg .u64 t; cvta.to.shared.u64 t, %1; cvt.u32.u64 %0, t; }"
        : "=r"(a) : "l"(p));
    return a;
}

static __device__ __forceinline__ void ldm_x4(uint32_t* r, uint32_t addr) {
    asm volatile(
        "ldmatrix.sync.aligned.m8n8.x4.shared.b16 {%0,%1,%2,%3}, [%4];"
        : "=r"(r[0]), "=r"(r[1]), "=r"(r[2]), "=r"(r[3]) : "r"(addr));
}

static __device__ __forceinline__ void mma_f16(float* d, const uint32_t* a,
                                               const uint32_t* b) {
    asm volatile(
        "mma.sync.aligned.m16n8k16.row.col.f32.f16.f16.f32 "
        "{%0,%1,%2,%3}, {%4,%5,%6,%7}, {%8,%9}, {%0,%1,%2,%3};"
        : "+f"(d[0]), "+f"(d[1]), "+f"(d[2]), "+f"(d[3])
        : "r"(a[0]), "r"(a[1]), "r"(a[2]), "r"(a[3]), "r"(b[0]), "r"(b[1]));
}

static __device__ __forceinline__ void cp16(uint32_t saddr, const void* gaddr) {
    asm volatile("cp.async.cg.shared.global [%0], [%1], 16;"
                 :: "r"(saddr), "l"(gaddr));
}

// Pack float4 -> 2 fp16x2 with single-instruction converts.
static __device__ __forceinline__ uint2 pack_hi4(const float4 v) {
    uint2 r;
    asm("cvt.rn.f16x2.f32 %0, %1, %2;" : "=r"(r.x) : "f"(v.y), "f"(v.x));
    asm("cvt.rn.f16x2.f32 %0, %1, %2;" : "=r"(r.y) : "f"(v.w), "f"(v.z));
    return r;
}

// ───────────── pre-pass: x fp32 -> swizzled fp16 tiles ─────────────
__global__ void __launch_bounds__(THREADS)
cvt_x_kernel(const float* __restrict__ x) {
    const int i = blockIdx.x;    // 0..63
    const int ch = blockIdx.y;   // 0..31
    unsigned char* tile = g_xh + ((size_t)i * NCHUNK + ch) * TILE_A;
    const float* src = x + (size_t)i * KDIM + ch * KC;
#pragma unroll
    for (int it = 0; it < 4; ++it) {
        int f = threadIdx.x + it * THREADS;   // float4 idx 0..1023
        int b = f >> 3;
        int c4 = f & 7;
        const float4 v = *reinterpret_cast<const float4*>(
            src + (size_t)b * (IDIM * KDIM) + c4 * 4);
        *reinterpret_cast<uint2*>(tile + SWZ64(b * 64 + c4 * 8)) = pack_hi4(v);
    }
}

// ───────────── main GEMM ─────────────

// cp.async one A fp16 tile (8 KB, already swizzled) into smem.
static __device__ __forceinline__ void stage_a(uint32_t dst,
                                               const unsigned char* tile) {
#pragma unroll
    for (int it = 0; it < 2; ++it) {
        int g = threadIdx.x + it * THREADS;   // 16B granule, 0..511
        cp16(dst + (uint32_t)(g * 16), tile + (size_t)g * 16);
    }
}

// LDG one B fp32 chunk [128 x 32] into registers (4 float4 per thread).
#define LDG_B(bregs, gb)                                                       \
    do {                                                                       \
        _Pragma("unroll") for (int it_ = 0; it_ < 4; ++it_) {                  \
            int f_ = threadIdx.x + it_ * THREADS;                              \
            int row_ = f_ >> 3, c4_ = f_ & 7;                                  \
            (bregs)[it_] = *reinterpret_cast<const float4*>(                   \
                (gb) + (size_t)row_ * 65536 + c4_ * 4);                        \
        }                                                                      \
    } while (0)

// Convert register-held B fp32 -> swizzled fp16 tile in smem.
#define CVT_B(bregs, sm, dst_off)                                              \
    do {                                                                       \
        _Pragma("unroll") for (int it_ = 0; it_ < 4; ++it_) {                  \
            int f_ = threadIdx.x + it_ * THREADS;                              \
            int row_ = f_ >> 3, c4_ = f_ & 7;                                  \
            *reinterpret_cast<uint2*>((sm) + (dst_off) +                       \
                                      SWZ64(row_ * 64 + c4_ * 8)) =            \
                pack_hi4((bregs)[it_]);                                        \
        }                                                                      \
    } while (0)

__global__ void __launch_bounds__(THREADS, 2)
fl_kernel(const float* __restrict__ w, const float* __restrict__ bias,
          float* __restrict__ out) {
    extern __shared__ char sm[];
    const uint32_t sbase = smem_u32(sm);
    const int tid = threadIdx.x;
    const int wid = tid >> 5;
    const int lid = tid & 31;
    const int warp_m = wid >> 2;   // 0..1 : 64 M rows each
    const int warp_n = wid & 3;    // 0..3 : 32 N cols each
    const int otile = blockIdx.x;  // 0..7
    const int i_idx = blockIdx.y;  // 0..63

    const unsigned char* xtiles = g_xh + (size_t)i_idx * NCHUNK * TILE_A;
    const float* wa = w + ((size_t)otile * 128) * (IDIM * KDIM) + (size_t)i_idx * KDIM;

    float acc[4][4][4];
#pragma unroll
    for (int a = 0; a < 4; ++a)
#pragma unroll
        for (int b = 0; b < 4; ++b)
#pragma unroll
            for (int c = 0; c < 4; ++c) acc[a][b][c] = 0.0f;

    const uint32_t a_row = (uint32_t)(warp_m * 64 + (lid & 15));
    const uint32_t a_cb = (uint32_t)((lid >> 4) * 16);
    const uint32_t b_row = (uint32_t)(warp_n * 32 + ((lid >> 4) << 3) + (lid & 7));
    const uint32_t b_cb = (uint32_t)(((lid >> 3) & 1) * 16);

    // Prologue: A chunks 0,1 via cp.async (groups 0,1); B chunk 0 converted,
    // B chunk 1 resident in regs.
    float4 bregs[4];
    stage_a(sbase + OFF_A + 0 * TILE_A, xtiles);
    asm volatile("cp.async.commit_group;" ::: "memory");
    stage_a(sbase + OFF_A + 1 * TILE_A, xtiles + TILE_A);
    asm volatile("cp.async.commit_group;" ::: "memory");
    LDG_B(bregs, wa);
    CVT_B(bregs, sm, OFF_B16 + 0 * TILE_B16);
    LDG_B(bregs, wa + KC);
    asm volatile("cp.async.wait_group 1;" ::: "memory");
    __syncthreads();

    int a_slot = 0;   // A buffer index of current chunk (mod 3)
    for (int ch = 0; ch < NCHUNK; ++ch) {
        const int a_next2 = (a_slot + 2 >= 3) ? (a_slot - 1) : (a_slot + 2);
        const bool pf = (ch + 2 < NCHUNK);

        // Prefetch A(ch+2) (group ch+2).
        if (pf) {
            stage_a(sbase + OFF_A + (uint32_t)(a_next2 * TILE_A),
                    xtiles + (size_t)(ch + 2) * TILE_A);
            asm volatile("cp.async.commit_group;" ::: "memory");
        }

        // MMA on A[a_slot], B16[ch&1]: 2 K=16 steps
        const uint32_t abuf = sbase + OFF_A + (uint32_t)(a_slot * TILE_A);
        const uint32_t bbuf = sbase + OFF_B16 + (uint32_t)((ch & 1) * TILE_B16);
#pragma unroll
        for (int ks = 0; ks < 2; ++ks) {
            uint32_t ah[4][4], bh[2][4];
#pragma unroll
            for (int mt = 0; mt < 4; ++mt)
                ldm_x4(ah[mt], abuf +
                       SWZ64((a_row + mt * 16) * 64 + ks * 32 + a_cb));
#pragma unroll
            for (int bt = 0; bt < 2; ++bt)
                ldm_x4(bh[bt], bbuf +
                       SWZ64((b_row + bt * 16) * 64 + ks * 32 + b_cb));
#pragma unroll
            for (int mt = 0; mt < 4; ++mt)
#pragma unroll
                for (int nt = 0; nt < 4; ++nt)
                    mma_f16(acc[mt][nt], ah[mt], &bh[nt >> 1][(nt & 1) * 2]);
        }

        // Convert B(ch+1) (resident in regs since last iteration), then load
        // B(ch+2) into regs — it has a full chunk (~4k cycles) to land before
        // its convert next iteration.
        if (ch + 1 < NCHUNK) {
            CVT_B(bregs, sm, OFF_B16 + (uint32_t)(((ch + 1) & 1) * TILE_B16));
            if (ch + 2 < NCHUNK) {
                LDG_B(bregs, wa + (ch + 2) * KC);
            }
        }

        // Ensure A(ch+1) landed (group ch+2 may stay in flight).
        if (pf) {
            asm volatile("cp.async.wait_group 1;" ::: "memory");
        } else {
            asm volatile("cp.async.wait_group 0;" ::: "memory");
        }
        __syncthreads();

        a_slot = (a_slot + 1 >= 3) ? 0 : (a_slot + 1);
    }

    // Epilogue: add bias, store. out[b][o][i] = b*65536 + o*64 + i
    const float* bp = bias + (size_t)(otile * 128) * IDIM + i_idx;
    float bv[4][2];
#pragma unroll
    for (int nt = 0; nt < 4; ++nt) {
        int n_l = warp_n * 32 + nt * 8 + 2 * (lid & 3);
        bv[nt][0] = bp[(size_t)n_l * IDIM];
        bv[nt][1] = bp[(size_t)(n_l + 1) * IDIM];
    }
#pragma unroll
    for (int mt = 0; mt < 4; ++mt) {
        int m0 = warp_m * 64 + mt * 16 + (lid >> 2);
#pragma unroll
        for (int nt = 0; nt < 4; ++nt) {
            int n_l = warp_n * 32 + nt * 8 + 2 * (lid & 3);
            float* o0 = out + (size_t)m0 * (ODIM * IDIM) +
                        (size_t)(otile * 128 + n_l) * IDIM + i_idx;
            o0[0] = acc[mt][nt][0] + bv[nt][0];
            o0[IDIM] = acc[mt][nt][1] + bv[nt][1];
            float* o8 = o0 + (size_t)8 * (ODIM * IDIM);
            o8[0] = acc[mt][nt][2] + bv[nt][0];
            o8[IDIM] = acc[mt][nt][3] + bv[nt][1];
        }
    }
}

extern "C" void kernel_launch(void* const* d_in, const int* in_sizes, int n_in,
                              void* d_out, int out_size) {
    (void)in_sizes; (void)n_in; (void)out_size;
    const float* x = (const float*)d_in[0];
    const float* w = (const float*)d_in[1];
    const float* bias = (const float*)d_in[2];
    float* out = (float*)d_out;

    cvt_x_kernel<<<dim3(IDIM, NCHUNK), THREADS>>>(x);

    cudaFuncSetAttribute(fl_kernel, cudaFuncAttributeMaxDynamicSharedMemorySize,
                         SMEM_DYN);
    fl_kernel<<<dim3(ODIM / 128, IDIM), THREADS, SMEM_DYN>>>(w, bias, out);
}